// round 3
// baseline (speedup 1.0000x reference)
#include <cuda_runtime.h>
#include <math.h>

#define NC 64
#define NF 128
#define NS 192      // NC + NF
#define SORT_N 256  // padded bitonic size

__global__ __launch_bounds__(192) void gridnerf_kernel(
    const float* __restrict__ ro,      // [N,3]
    const float* __restrict__ rd,      // [N,3]
    const float* __restrict__ cw,      // [N,NC]
    const float* __restrict__ ct,      // [N,NC]
    const float* __restrict__ uu_in,   // [N,NF]
    const float* __restrict__ colors,  // [N,NS,3]
    const float* __restrict__ dens,    // [N,NS]
    float* __restrict__ out_rgb,       // [N,3]
    float* __restrict__ out_depth,     // [N]
    float* __restrict__ out_op,        // [N]
    float* __restrict__ out_fp)        // [N,NS,3]
{
    const int ray  = blockIdx.x;
    const int tid  = threadIdx.x;
    const int lane = tid & 31;
    const int wid  = tid >> 5;

    __shared__ float s_cdf[NC + 1];
    __shared__ float s_ct[NC];
    __shared__ float s_t[SORT_N];
    __shared__ float s_w[8];    // warp partials
    __shared__ float s_wx[8];   // warp exclusive prefixes
    __shared__ float s_vec[6];  // o(3), d(3)
    __shared__ float s_red[48]; // 6 warps x 5 values (padded stride 8)

    if (tid < 3)       s_vec[tid] = ro[(size_t)ray * 3 + tid];
    else if (tid < 6)  s_vec[tid] = rd[(size_t)ray * 3 + (tid - 3)];

    // ---- Phase 1: weights -> pdf -> cdf (threads 0..63, warps 0/1) ----
    float wv = 0.f;
    if (tid < NC) {
        wv = cw[(size_t)ray * NC + tid] + 1e-5f;
        s_ct[tid] = ct[(size_t)ray * NC + tid];
    }
    // sum of 64 (two full warps reduce, combine via shared)
    float sumv = wv;
    #pragma unroll
    for (int off = 16; off; off >>= 1)
        sumv += __shfl_xor_sync(0xffffffffu, sumv, off);
    if (tid < NC && lane == 0) s_w[wid] = sumv;
    __syncthreads();
    const float total = s_w[0] + s_w[1];

    if (tid < NC) {
        float v = wv / total;  // pdf
        #pragma unroll
        for (int off = 1; off < 32; off <<= 1) {
            float n = __shfl_up_sync(0xffffffffu, v, off);
            if (lane >= off) v += n;
        }
        if (lane == 31) s_wx[wid] = v;  // warp inclusive total
        s_cdf[tid + 1] = v;             // warp-local inclusive for now
    }
    if (tid == 0) s_cdf[0] = 0.f;
    __syncthreads();
    if (tid >= 32 && tid < 64) s_cdf[tid + 1] += s_wx[0];
    __syncthreads();

    // ---- Phase 2: inverse-CDF fine sampling (threads 0..127) ----
    float ft = 0.f;
    if (tid < NF) {
        const float uu = uu_in[(size_t)ray * NF + tid];
        int lo = 0, hi = NC + 1;  // upper_bound: first idx with cdf[idx] > uu
        #pragma unroll 7
        while (lo < hi) {
            int mid = (lo + hi) >> 1;
            if (s_cdf[mid] <= uu) lo = mid + 1; else hi = mid;
        }
        int below = min(max(lo - 1, 0), NC - 1);
        int above = min(lo, NC - 1);
        float cb = s_cdf[below], ca = s_cdf[above];
        float tb = s_ct[below],  ta = s_ct[above];
        float denom = ca - cb;
        if (denom < 1e-5f) denom = 1.f;
        float tt = (uu - cb) / denom;
        ft = tb + tt * (ta - tb);
    }

    // ---- Phase 3: combine + bitonic sort (256 padded, 128 pairs/stage) ----
    if (tid < NC) s_t[tid] = s_ct[tid];
    if (tid < NF) s_t[NC + tid] = ft;
    if (tid >= 128) s_t[64 + tid] = 3.4e38f;  // tid 128..191 -> [192..255] pad

    for (int k = 2; k <= SORT_N; k <<= 1) {
        for (int j = k >> 1; j > 0; j >>= 1) {
            __syncthreads();
            if (tid < 128) {
                int i = tid + (tid & ~(j - 1));
                int p = i + j;
                bool up = (i & k) == 0;
                float a = s_t[i], b = s_t[p];
                if ((a > b) == up) { s_t[i] = b; s_t[p] = a; }
            }
        }
    }
    __syncthreads();

    // ---- Phase 4: fine points + volume rendering (all 192 threads) ----
    const float ox = s_vec[0], oy = s_vec[1], oz = s_vec[2];
    const float dx = s_vec[3], dy = s_vec[4], dz = s_vec[5];
    const float dnorm = sqrtf(dx * dx + dy * dy + dz * dz);

    const float tval = s_t[tid];
    float* fp = out_fp + (size_t)ray * (NS * 3) + tid * 3;
    fp[0] = ox + dx * tval;
    fp[1] = oy + dy * tval;
    fp[2] = oz + dz * tval;

    float dist = (tid < NS - 1) ? (s_t[tid + 1] - tval) : 1e10f;
    dist *= dnorm;
    const float dv = dens[(size_t)ray * NS + tid];
    const float alpha = 1.f - expf(-dv * dist);
    const float p = 1.f - alpha + 1e-10f;

    // 6-warp exclusive prefix product of p -> transmittance T
    float v = p;
    #pragma unroll
    for (int off = 1; off < 32; off <<= 1) {
        float n = __shfl_up_sync(0xffffffffu, v, off);
        if (lane >= off) v *= n;
    }
    float exclw = __shfl_up_sync(0xffffffffu, v, 1);
    if (lane == 0) exclw = 1.f;
    if (lane == 31) s_w[wid] = v;  // warp total product
    __syncthreads();
    if (tid == 0) {
        float acc = 1.f;
        #pragma unroll
        for (int w = 0; w < 6; w++) { float t = s_w[w]; s_wx[w] = acc; acc *= t; }
    }
    __syncthreads();
    const float T = s_wx[wid] * exclw;
    const float wgt = alpha * T;

    const float* col = colors + (size_t)ray * (NS * 3) + tid * 3;
    float r = wgt * col[0];
    float g = wgt * col[1];
    float b = wgt * col[2];
    float dep = wgt * tval;
    float op  = wgt;

    #pragma unroll
    for (int off = 16; off; off >>= 1) {
        r   += __shfl_xor_sync(0xffffffffu, r, off);
        g   += __shfl_xor_sync(0xffffffffu, g, off);
        b   += __shfl_xor_sync(0xffffffffu, b, off);
        dep += __shfl_xor_sync(0xffffffffu, dep, off);
        op  += __shfl_xor_sync(0xffffffffu, op, off);
    }
    if (lane == 0) {
        s_red[wid]      = r;
        s_red[8 + wid]  = g;
        s_red[16 + wid] = b;
        s_red[24 + wid] = dep;
        s_red[32 + wid] = op;
    }
    __syncthreads();
    if (tid == 0) {
        float R = 0, G = 0, B = 0, D = 0, O = 0;
        #pragma unroll
        for (int w = 0; w < 6; w++) {
            R += s_red[w]; G += s_red[8 + w]; B += s_red[16 + w];
            D += s_red[24 + w]; O += s_red[32 + w];
        }
        out_rgb[(size_t)ray * 3 + 0] = R;
        out_rgb[(size_t)ray * 3 + 1] = G;
        out_rgb[(size_t)ray * 3 + 2] = B;
        out_depth[ray] = D;
        out_op[ray]    = O;
    }
}

extern "C" void kernel_launch(void* const* d_in, const int* in_sizes, int n_in,
                              void* d_out, int out_size)
{
    const float* ro     = (const float*)d_in[0];  // ray_origins   [N,3]
    const float* rd     = (const float*)d_in[1];  // ray_directions[N,3]
    const float* cw     = (const float*)d_in[2];  // coarse_weights[N,NC]
    const float* ct     = (const float*)d_in[3];  // coarse_t_vals [N,NC]
    const float* u      = (const float*)d_in[4];  // u             [N,NF]
    const float* colors = (const float*)d_in[5];  // colors        [N,NS,3]
    const float* dens   = (const float*)d_in[6];  // densities     [N,NS,1]

    const int N = in_sizes[0] / 3;

    float* out       = (float*)d_out;
    float* out_rgb   = out;                       // [N,3]
    float* out_depth = out + (size_t)N * 3;       // [N]
    float* out_op    = out_depth + N;             // [N]
    float* out_fp    = out_op + N;                // [N,NS,3]

    gridnerf_kernel<<<N, 192>>>(ro, rd, cw, ct, u, colors, dens,
                                out_rgb, out_depth, out_op, out_fp);
}

// round 4
// speedup vs baseline: 1.4173x; 1.4173x over previous
#include <cuda_runtime.h>
#include <math.h>

#define NC 64
#define NF 128
#define NS 192      // NC + NF

__global__ __launch_bounds__(192) void gridnerf_kernel(
    const float* __restrict__ ro,      // [N,3]
    const float* __restrict__ rd,      // [N,3]
    const float* __restrict__ cw,      // [N,NC]
    const float* __restrict__ ct,      // [N,NC]
    const float* __restrict__ uu_in,   // [N,NF]
    const float* __restrict__ colors,  // [N,NS,3]
    const float* __restrict__ dens,    // [N,NS]
    float* __restrict__ out_rgb,       // [N,3]
    float* __restrict__ out_depth,     // [N]
    float* __restrict__ out_op,        // [N]
    float* __restrict__ out_fp)        // [N,NS,3]
{
    const int ray  = blockIdx.x;
    const int tid  = threadIdx.x;
    const int lane = tid & 31;
    const int wid  = tid >> 5;

    __shared__ float s_cdf[NC + 1];
    __shared__ float s_ct[NC];
    __shared__ float s_f[NF];    // sorted fine values (also cross-warp sort scratch)
    __shared__ float s_t[NS];    // merged sorted t
    __shared__ float s_w[8];     // warp partials
    __shared__ float s_wx[8];    // warp exclusive prefixes
    __shared__ float s_vec[6];   // o(3), d(3)
    __shared__ float s_red[48];  // 6 warps x 5 values (stride 8)

    // ---- Prefetch per-sample global data (independent of the sort) ----
    const float* col = colors + (size_t)ray * (NS * 3) + tid * 3;
    const float c0 = col[0], c1 = col[1], c2 = col[2];
    const float dv = dens[(size_t)ray * NS + tid];

    if (tid < 3)       s_vec[tid] = ro[(size_t)ray * 3 + tid];
    else if (tid < 6)  s_vec[tid] = rd[(size_t)ray * 3 + (tid - 3)];

    // ---- Phase 1: weights -> pdf -> cdf (threads 0..63) ----
    float wv = 0.f;
    if (tid < NC) {
        wv = cw[(size_t)ray * NC + tid] + 1e-5f;
        s_ct[tid] = ct[(size_t)ray * NC + tid];
    }
    float sumv = wv;
    #pragma unroll
    for (int off = 16; off; off >>= 1)
        sumv += __shfl_xor_sync(0xffffffffu, sumv, off);
    if (tid < NC && lane == 0) s_w[wid] = sumv;
    __syncthreads();
    const float total = s_w[0] + s_w[1];

    if (tid < NC) {
        float v = wv / total;  // pdf
        #pragma unroll
        for (int off = 1; off < 32; off <<= 1) {
            float n = __shfl_up_sync(0xffffffffu, v, off);
            if (lane >= off) v += n;
        }
        if (lane == 31) s_wx[wid] = v;
        s_cdf[tid + 1] = v;
    }
    if (tid == 0) s_cdf[0] = 0.f;
    __syncthreads();
    if (tid >= 32 && tid < 64) s_cdf[tid + 1] += s_wx[0];
    __syncthreads();

    // ---- Phase 2: inverse-CDF fine sampling (threads 0..127) ----
    float fv = 0.f;
    if (tid < NF) {
        const float uu = uu_in[(size_t)ray * NF + tid];
        int lo = 0, hi = NC + 1;  // upper_bound: first idx with cdf[idx] > uu
        while (lo < hi) {
            int mid = (lo + hi) >> 1;
            if (s_cdf[mid] <= uu) lo = mid + 1; else hi = mid;
        }
        int below = min(max(lo - 1, 0), NC - 1);
        int above = min(lo, NC - 1);
        float cb = s_cdf[below], ca = s_cdf[above];
        float tb = s_ct[below],  ta = s_ct[above];
        float denom = ca - cb;
        if (denom < 1e-5f) denom = 1.f;
        float tt = (uu - cb) / denom;
        fv = tb + tt * (ta - tb);
    }

    // ---- Phase 3a: bitonic sort of 128 fine values, registers + shfl ----
    // threads 0..127 (warps 0-3) hold one value each; warps 4-5 idle through.
    #pragma unroll
    for (int k = 2; k <= NF; k <<= 1) {
        #pragma unroll
        for (int j = k >> 1; j > 0; j >>= 1) {
            float w;
            if (j < 32) {
                w = __shfl_xor_sync(0xffffffffu, fv, j);
            } else {
                __syncthreads();
                if (tid < NF) s_f[tid] = fv;
                __syncthreads();
                w = (tid < NF) ? s_f[tid ^ j] : 0.f;
            }
            if (tid < NF) {
                bool up    = (tid & k) == 0;
                bool lower = (tid & j) == 0;
                float mn = fminf(fv, w), mx = fmaxf(fv, w);
                fv = (up == lower) ? mn : mx;
            }
        }
    }
    __syncthreads();
    if (tid < NF) s_f[tid] = fv;   // sorted fine values
    __syncthreads();

    // ---- Phase 3b: merge-path scatter into s_t ----
    if (tid < NF) {
        // count coarse <= fv  (upper bound over s_ct[0..63])
        int lo = 0, hi = NC;
        #pragma unroll 6
        while (lo < hi) {
            int mid = (lo + hi) >> 1;
            if (s_ct[mid] <= fv) lo = mid + 1; else hi = mid;
        }
        s_t[tid + lo] = fv;
    } else {
        const int i = tid - NF;         // 0..63, warps 4-5
        const float cv = s_ct[i];
        // count fine < cv  (lower bound over s_f[0..127])
        int lo = 0, hi = NF;
        #pragma unroll 7
        while (lo < hi) {
            int mid = (lo + hi) >> 1;
            if (s_f[mid] < cv) lo = mid + 1; else hi = mid;
        }
        s_t[i + lo] = cv;
    }
    __syncthreads();

    // ---- Phase 4: fine points + volume rendering (all 192 threads) ----
    const float ox = s_vec[0], oy = s_vec[1], oz = s_vec[2];
    const float dx = s_vec[3], dy = s_vec[4], dz = s_vec[5];
    const float dnorm = sqrtf(dx * dx + dy * dy + dz * dz);

    const float tval = s_t[tid];
    float* fp = out_fp + (size_t)ray * (NS * 3) + tid * 3;
    fp[0] = ox + dx * tval;
    fp[1] = oy + dy * tval;
    fp[2] = oz + dz * tval;

    float dist = (tid < NS - 1) ? (s_t[tid + 1] - tval) : 1e10f;
    dist *= dnorm;
    const float alpha = 1.f - __expf(-dv * dist);
    const float p = 1.f - alpha + 1e-10f;

    // 6-warp exclusive prefix product of p -> transmittance T
    float v = p;
    #pragma unroll
    for (int off = 1; off < 32; off <<= 1) {
        float n = __shfl_up_sync(0xffffffffu, v, off);
        if (lane >= off) v *= n;
    }
    float exclw = __shfl_up_sync(0xffffffffu, v, 1);
    if (lane == 0) exclw = 1.f;
    if (lane == 31) s_w[wid] = v;
    __syncthreads();
    if (tid == 0) {
        float acc = 1.f;
        #pragma unroll
        for (int w = 0; w < 6; w++) { float t = s_w[w]; s_wx[w] = acc; acc *= t; }
    }
    __syncthreads();
    const float T = s_wx[wid] * exclw;
    const float wgt = alpha * T;

    float r = wgt * c0;
    float g = wgt * c1;
    float b = wgt * c2;
    float dep = wgt * tval;
    float op  = wgt;

    #pragma unroll
    for (int off = 16; off; off >>= 1) {
        r   += __shfl_xor_sync(0xffffffffu, r, off);
        g   += __shfl_xor_sync(0xffffffffu, g, off);
        b   += __shfl_xor_sync(0xffffffffu, b, off);
        dep += __shfl_xor_sync(0xffffffffu, dep, off);
        op  += __shfl_xor_sync(0xffffffffu, op, off);
    }
    if (lane == 0) {
        s_red[wid]      = r;
        s_red[8 + wid]  = g;
        s_red[16 + wid] = b;
        s_red[24 + wid] = dep;
        s_red[32 + wid] = op;
    }
    __syncthreads();
    if (tid == 0) {
        float R = 0, G = 0, B = 0, D = 0, O = 0;
        #pragma unroll
        for (int w = 0; w < 6; w++) {
            R += s_red[w]; G += s_red[8 + w]; B += s_red[16 + w];
            D += s_red[24 + w]; O += s_red[32 + w];
        }
        out_rgb[(size_t)ray * 3 + 0] = R;
        out_rgb[(size_t)ray * 3 + 1] = G;
        out_rgb[(size_t)ray * 3 + 2] = B;
        out_depth[ray] = D;
        out_op[ray]    = O;
    }
}

extern "C" void kernel_launch(void* const* d_in, const int* in_sizes, int n_in,
                              void* d_out, int out_size)
{
    const float* ro     = (const float*)d_in[0];
    const float* rd     = (const float*)d_in[1];
    const float* cw     = (const float*)d_in[2];
    const float* ct     = (const float*)d_in[3];
    const float* u      = (const float*)d_in[4];
    const float* colors = (const float*)d_in[5];
    const float* dens   = (const float*)d_in[6];

    const int N = in_sizes[0] / 3;

    float* out       = (float*)d_out;
    float* out_rgb   = out;                 // [N,3]
    float* out_depth = out + (size_t)N * 3; // [N]
    float* out_op    = out_depth + N;       // [N]
    float* out_fp    = out_op + N;          // [N,NS,3]

    gridnerf_kernel<<<N, 192>>>(ro, rd, cw, ct, u, colors, dens,
                                out_rgb, out_depth, out_op, out_fp);
}

// round 5
// speedup vs baseline: 2.0849x; 1.4710x over previous
#include <cuda_runtime.h>
#include <math.h>

#define NC 64
#define NF 128
#define NS 192      // NC + NF

__global__ __launch_bounds__(192) void gridnerf_kernel(
    const float* __restrict__ ro,      // [N,3]
    const float* __restrict__ rd,      // [N,3]
    const float* __restrict__ cw,      // [N,NC]
    const float* __restrict__ ct,      // [N,NC]
    const float* __restrict__ uu_in,   // [N,NF]
    const float* __restrict__ colors,  // [N,NS,3]
    const float* __restrict__ dens,    // [N,NS]
    float* __restrict__ out_rgb,       // [N,3]
    float* __restrict__ out_depth,     // [N]
    float* __restrict__ out_op,        // [N]
    float* __restrict__ out_fp)        // [N,NS,3]
{
    const int ray  = blockIdx.x;
    const int tid  = threadIdx.x;
    const int lane = tid & 31;
    const int wid  = tid >> 5;

    __shared__ float s_cdf[128];   // [0..64] real, [65..127] = +inf pad
    __shared__ float s_ct[NC];
    __shared__ float s_f[NF];      // sort cross-warp scratch
    __shared__ float s_t[NS];      // merged sorted t
    __shared__ int   s_lo[192];    // [0..127] sorted lo, [128..191] = INT_MAX pad
    __shared__ float s_w[8];       // warp partial products
    __shared__ float s_wx[8];      // warp exclusive prefixes
    __shared__ float s_vec[6];     // o(3), d(3)
    __shared__ float s_red[40];    // 5 metrics x 8 (stride 8)

    // ---- Prefetch per-sample global data (independent of sort order) ----
    const float* col = colors + (size_t)ray * (NS * 3) + tid * 3;
    const float c0 = col[0], c1 = col[1], c2 = col[2];
    const float dv = dens[(size_t)ray * NS + tid];

    float uu = 0.f;
    if (tid < NF) {
        // fine lanes: load u, will sort it (inverse-CDF is monotone in u)
        uu = uu_in[(size_t)ray * NF + tid];
    } else if (tid < 160) {
        // ---- warp 4: build cdf solo (2 elements per lane, warp-local scan) ----
        const int l = tid - 128;                      // == lane
        const float2 w2 = reinterpret_cast<const float2*>(cw + (size_t)ray * NC)[l];
        const float a = w2.x + 1e-5f;
        const float b = w2.y + 1e-5f;
        const float ps = a + b;                       // pair sum (elems 2l, 2l+1)
        float inc = ps;
        #pragma unroll
        for (int off = 1; off < 32; off <<= 1) {
            float n = __shfl_up_sync(0xffffffffu, inc, off);
            if (lane >= off) inc += n;
        }
        const float total = __shfl_sync(0xffffffffu, inc, 31);
        const float inv = 1.f / total;
        const float excl = inc - ps;
        s_cdf[2 * l + 1] = (excl + a) * inv;
        s_cdf[2 * l + 2] = (excl + ps) * inv;
        if (l == 0) s_cdf[0] = 0.f;
        s_lo[tid] = 0x7fffffff;                       // pad lo[128..159]
    } else {
        // ---- warp 5: ct load, pads, ray vectors ----
        const int l = tid - 160;
        const float2 t2 = reinterpret_cast<const float2*>(ct + (size_t)ray * NC)[l];
        s_ct[2 * l]     = t2.x;
        s_ct[2 * l + 1] = t2.y;
        s_cdf[65 + l] = 3.4e38f;
        if (l < 31) s_cdf[97 + l] = 3.4e38f;
        s_lo[tid] = 0x7fffffff;                       // pad lo[160..191]
        if (l < 3)      s_vec[l] = ro[(size_t)ray * 3 + l];
        else if (l < 6) s_vec[l] = rd[(size_t)ray * 3 + (l - 3)];
    }

    // ---- Bitonic sort of 128 u-values (registers+shfl; 3 shared substages).
    //      Warps 4-5 join only at the barriers (their setup above overlaps
    //      with the first 15 shfl-only substages of warps 0-3). ----
    #pragma unroll
    for (int k = 2; k <= NF; k <<= 1) {
        #pragma unroll
        for (int j = k >> 1; j > 0; j >>= 1) {
            if (j >= 32) {
                __syncthreads();
                if (tid < NF) s_f[tid] = uu;
                __syncthreads();
                if (tid < NF) {
                    float w = s_f[tid ^ j];
                    bool dir = ((tid & k) == 0) == ((tid & j) == 0);
                    uu = dir ? fminf(uu, w) : fmaxf(uu, w);
                }
            } else if (tid < NF) {
                float w = __shfl_xor_sync(0xffffffffu, uu, j);
                bool dir = ((tid & k) == 0) == ((tid & j) == 0);
                uu = dir ? fminf(uu, w) : fmaxf(uu, w);
            }
        }
    }
    // s_cdf/s_ct writes are visible via the in-loop barriers.

    // ---- Phase 2: branchless inverse-CDF on sorted u; direct scatter ----
    if (tid < NF) {
        int p = 0;                                    // invariant: s_cdf[p] <= uu
        if (s_cdf[64]     <= uu) p = 64;
        if (s_cdf[p + 32] <= uu) p += 32;
        if (s_cdf[p + 16] <= uu) p += 16;
        if (s_cdf[p + 8]  <= uu) p += 8;
        if (s_cdf[p + 4]  <= uu) p += 4;
        if (s_cdf[p + 2]  <= uu) p += 2;
        if (s_cdf[p + 1]  <= uu) p += 1;
        const int lo    = p + 1;                      // searchsorted right
        const int below = min(p, NC - 1);
        const int above = min(lo, NC - 1);
        const float cb = s_cdf[below], ca = s_cdf[above];
        const float tb = s_ct[below],  ta = s_ct[above];
        float denom = ca - cb;
        if (denom < 1e-5f) denom = 1.f;
        const float tt = (uu - cb) / denom;
        const float fv = tb + tt * (ta - tb);
        s_lo[tid] = lo;                               // monotone (u sorted)
        s_t[tid + min(lo, NC)] = fv;                  // rank-merge scatter
    }
    __syncthreads();

    // ---- Coarse merge ranks: count fine with lo <= i (8-step branchless) ----
    if (tid >= NF) {
        const int i = tid - NF;                       // 0..63
        int r = 0;
        if (s_lo[127]    <= i) r = 128;
        if (s_lo[r + 63] <= i) r += 64;
        if (s_lo[r + 31] <= i) r += 32;
        if (s_lo[r + 15] <= i) r += 16;
        if (s_lo[r + 7]  <= i) r += 8;
        if (s_lo[r + 3]  <= i) r += 4;
        if (s_lo[r + 1]  <= i) r += 2;
        if (s_lo[r]      <= i) r += 1;
        s_t[i + r] = s_ct[i];
    }
    __syncthreads();

    // ---- Phase 4: fine points + volume rendering (all 192 threads) ----
    const float ox = s_vec[0], oy = s_vec[1], oz = s_vec[2];
    const float dx = s_vec[3], dy = s_vec[4], dz = s_vec[5];
    const float dnorm = sqrtf(dx * dx + dy * dy + dz * dz);

    const float tval = s_t[tid];
    float* fp = out_fp + (size_t)ray * (NS * 3) + tid * 3;
    fp[0] = ox + dx * tval;
    fp[1] = oy + dy * tval;
    fp[2] = oz + dz * tval;

    float dist = (tid < NS - 1) ? (s_t[tid + 1] - tval) : 1e10f;
    dist *= dnorm;
    const float alpha = 1.f - __expf(-dv * dist);
    const float p = 1.f - alpha + 1e-10f;

    // 6-warp exclusive prefix product -> transmittance T
    float v = p;
    #pragma unroll
    for (int off = 1; off < 32; off <<= 1) {
        float n = __shfl_up_sync(0xffffffffu, v, off);
        if (lane >= off) v *= n;
    }
    float exclw = __shfl_up_sync(0xffffffffu, v, 1);
    if (lane == 0) exclw = 1.f;
    if (lane == 31) s_w[wid] = v;
    __syncthreads();
    if (tid == 0) {
        float acc = 1.f;
        #pragma unroll
        for (int w = 0; w < 6; w++) { float t = s_w[w]; s_wx[w] = acc; acc *= t; }
    }
    __syncthreads();
    const float T = s_wx[wid] * exclw;
    const float wgt = alpha * T;

    float r = wgt * c0;
    float g = wgt * c1;
    float b = wgt * c2;
    float dep = wgt * tval;
    float op  = wgt;

    #pragma unroll
    for (int off = 16; off; off >>= 1) {
        r   += __shfl_xor_sync(0xffffffffu, r, off);
        g   += __shfl_xor_sync(0xffffffffu, g, off);
        b   += __shfl_xor_sync(0xffffffffu, b, off);
        dep += __shfl_xor_sync(0xffffffffu, dep, off);
        op  += __shfl_xor_sync(0xffffffffu, op, off);
    }
    if (lane == 0) {
        s_red[wid]      = r;
        s_red[8 + wid]  = g;
        s_red[16 + wid] = b;
        s_red[24 + wid] = dep;
        s_red[32 + wid] = op;
    }
    __syncthreads();
    if (tid < 5) {
        const float* sr = s_red + tid * 8;
        float acc = sr[0] + sr[1] + sr[2] + sr[3] + sr[4] + sr[5];
        float* dst = (tid < 3) ? (out_rgb + (size_t)ray * 3 + tid)
                   : (tid == 3) ? (out_depth + ray) : (out_op + ray);
        *dst = acc;
    }
}

extern "C" void kernel_launch(void* const* d_in, const int* in_sizes, int n_in,
                              void* d_out, int out_size)
{
    const float* ro     = (const float*)d_in[0];
    const float* rd     = (const float*)d_in[1];
    const float* cw     = (const float*)d_in[2];
    const float* ct     = (const float*)d_in[3];
    const float* u      = (const float*)d_in[4];
    const float* colors = (const float*)d_in[5];
    const float* dens   = (const float*)d_in[6];

    const int N = in_sizes[0] / 3;

    float* out       = (float*)d_out;
    float* out_rgb   = out;                 // [N,3]
    float* out_depth = out + (size_t)N * 3; // [N]
    float* out_op    = out_depth + N;       // [N]
    float* out_fp    = out_op + N;          // [N,NS,3]

    gridnerf_kernel<<<N, 192>>>(ro, rd, cw, ct, u, colors, dens,
                                out_rgb, out_depth, out_op, out_fp);
}

// round 6
// speedup vs baseline: 4.0208x; 1.9286x over previous
#include <cuda_runtime.h>
#include <math.h>

#define NC 64
#define NF 128
#define NS 192
#define RPB 8        // rays per block, 1 warp each

// compare-exchange a pair of registers; 'up' => a gets min
#define CEPAIR(a, b, up) { float _mn = fminf(a, b), _mx = fmaxf(a, b); \
                           a = (up) ? _mn : _mx; b = (up) ? _mx : _mn; }

__global__ __launch_bounds__(256) void gridnerf_kernel(
    const float* __restrict__ ro,      // [N,3]
    const float* __restrict__ rd,      // [N,3]
    const float* __restrict__ cw,      // [N,NC]
    const float* __restrict__ ct,      // [N,NC]
    const float* __restrict__ uu_in,   // [N,NF]
    const float* __restrict__ colors,  // [N,NS,3]
    const float* __restrict__ dens,    // [N,NS]
    float* __restrict__ out_rgb,       // [N,3]
    float* __restrict__ out_depth,     // [N]
    float* __restrict__ out_op,        // [N]
    float* __restrict__ out_fp,        // [N,NS,3]
    int nrays)
{
    const int L   = threadIdx.x & 31;
    const int w   = threadIdx.x >> 5;
    const int ray = blockIdx.x * RPB + w;
    if (ray >= nrays) return;          // whole-warp uniform exit; no block syncs used

    __shared__ float sh_cdf[RPB][128]; // [0..64] cdf, [65..127] +inf pad
    __shared__ float sh_ct [RPB][64];
    __shared__ int   sh_lo [RPB][192]; // [0..127] lo (sorted), [128..191] INT_MAX pad
    __shared__ float sh_t  [RPB][192];
    __shared__ float sh_w  [RPB][192];
    __shared__ float sh_dv [RPB][192];

    float* cdf = sh_cdf[w];
    float* sct = sh_ct[w];
    int*   slo = sh_lo[w];
    float* st  = sh_t[w];
    float* sw  = sh_w[w];
    float* sdv = sh_dv[w];

    // ---- A: global loads (coalesced / vectorized) ----
    const float4 u4 = ((const float4*)(uu_in + (size_t)ray * NF))[L];
    float v0 = u4.x, v1 = u4.y, v2 = u4.z, v3 = u4.w;   // elements 4L..4L+3

    const float2 cw2 = ((const float2*)(cw + (size_t)ray * NC))[L];
    const float2 ct2 = ((const float2*)(ct + (size_t)ray * NC))[L];

    #pragma unroll
    for (int i = 0; i < 6; i++)
        sdv[32 * i + L] = dens[(size_t)ray * NS + 32 * i + L];

    const float ox = ro[3 * ray + 0], oy = ro[3 * ray + 1], oz = ro[3 * ray + 2];
    const float dx = rd[3 * ray + 0], dy = rd[3 * ray + 1], dz = rd[3 * ray + 2];
    const float dnorm = sqrtf(dx * dx + dy * dy + dz * dz);

    // ---- B: cdf build (pair-per-lane warp scan) ----
    {
        const float a  = cw2.x + 1e-5f;
        const float b  = cw2.y + 1e-5f;
        const float ps = a + b;
        float inc = ps;
        #pragma unroll
        for (int off = 1; off < 32; off <<= 1) {
            float n = __shfl_up_sync(0xffffffffu, inc, off);
            if (L >= off) inc += n;
        }
        const float total = __shfl_sync(0xffffffffu, inc, 31);
        const float invt  = 1.f / total;
        const float excl  = inc - ps;
        cdf[2 * L + 1] = (excl + a) * invt;
        cdf[2 * L + 2] = (excl + ps) * invt;
        if (L == 0) cdf[0] = 0.f;
        cdf[65 + L] = 3.4e38f;
        if (L < 31) cdf[97 + L] = 3.4e38f;
        sct[2 * L]     = ct2.x;
        sct[2 * L + 1] = ct2.y;
        slo[128 + L] = 0x7fffffff;
        slo[160 + L] = 0x7fffffff;
    }
    __syncwarp();

    // ---- C: bitonic sort of 128 u, 4 elements/thread (e = 4L+i) ----
    #pragma unroll
    for (int k = 2; k <= 128; k <<= 1) {
        #pragma unroll
        for (int j = k >> 1; j >= 4; j >>= 1) {
            const bool up = ((L & (k >> 2)) == 0);   // k>=8 here
            const bool lw = ((L & (j >> 2)) == 0);
            const bool km = (up == lw);
            float w0 = __shfl_xor_sync(0xffffffffu, v0, j >> 2);
            float w1 = __shfl_xor_sync(0xffffffffu, v1, j >> 2);
            float w2 = __shfl_xor_sync(0xffffffffu, v2, j >> 2);
            float w3 = __shfl_xor_sync(0xffffffffu, v3, j >> 2);
            v0 = km ? fminf(v0, w0) : fmaxf(v0, w0);
            v1 = km ? fminf(v1, w1) : fmaxf(v1, w1);
            v2 = km ? fminf(v2, w2) : fmaxf(v2, w2);
            v3 = km ? fminf(v3, w3) : fmaxf(v3, w3);
        }
        if (k >= 4) {  // j = 2 : pairs (v0,v2), (v1,v3); e&k uniform per thread
            const bool up = (k == 4) ? ((L & 1) == 0) : ((L & (k >> 2)) == 0);
            CEPAIR(v0, v2, up); CEPAIR(v1, v3, up);
        }
        // j = 1 : pairs (v0,v1), (v2,v3)
        if (k == 2) {
            CEPAIR(v0, v1, true);  CEPAIR(v2, v3, false);
        } else {
            const bool up = (k == 4) ? ((L & 1) == 0) : ((L & (k >> 2)) == 0);
            CEPAIR(v0, v1, up);    CEPAIR(v2, v3, up);
        }
    }

    // ---- D: inverse-CDF on sorted u + rank-merge scatter of fine values ----
    {
        float va[4] = {v0, v1, v2, v3};
        #pragma unroll
        for (int i = 0; i < 4; i++) {
            const float uu = va[i];
            int p = 0;                                // invariant cdf[p] <= uu
            if (cdf[64]     <= uu) p = 64;
            if (cdf[p + 32] <= uu) p += 32;
            if (cdf[p + 16] <= uu) p += 16;
            if (cdf[p + 8]  <= uu) p += 8;
            if (cdf[p + 4]  <= uu) p += 4;
            if (cdf[p + 2]  <= uu) p += 2;
            if (cdf[p + 1]  <= uu) p += 1;
            const int lo    = p + 1;                  // searchsorted(right)
            const int below = min(p, NC - 1);
            const int above = min(lo, NC - 1);
            const float cb = cdf[below], ca = cdf[above];
            const float tb = sct[below], ta = sct[above];
            float denom = ca - cb;
            if (denom < 1e-5f) denom = 1.f;
            const float tt = (uu - cb) / denom;
            const float fv = tb + tt * (ta - tb);
            const int e = 4 * L + i;                  // sorted rank
            slo[e] = lo;                              // monotone
            st[e + min(lo, NC)] = fv;
        }
    }
    __syncwarp();

    // ---- E: coarse ranks (count fine with lo <= i), 2 per lane ----
    #pragma unroll
    for (int h = 0; h < 2; h++) {
        const int i = L + 32 * h;
        int r = 0;
        if (slo[127]    <= i) r = 128;
        if (slo[r + 63] <= i) r += 64;
        if (slo[r + 31] <= i) r += 32;
        if (slo[r + 15] <= i) r += 16;
        if (slo[r + 7]  <= i) r += 8;
        if (slo[r + 3]  <= i) r += 4;
        if (slo[r + 1]  <= i) r += 2;
        if (slo[r]      <= i) r += 1;
        st[i + r] = sct[i];
    }
    __syncwarp();

    // issue color loads now (consumed in G; F below hides the latency)
    float2 cv[9];
    {
        const float2* c2 = (const float2*)(colors + (size_t)ray * (NS * 3));
        #pragma unroll
        for (int i = 0; i < 9; i++) cv[i] = c2[32 * i + L];
    }

    // ---- F: alpha + transmittance (blocked: thread owns samples 6L..6L+5) ----
    float dep = 0.f, op = 0.f;
    {
        float tb[6], dvv[6], alpha[6], lex[6];
        #pragma unroll
        for (int i = 0; i < 6; i++) tb[i]  = st[6 * L + i];
        const float t6 = (L < 31) ? st[6 * L + 6] : 0.f;
        #pragma unroll
        for (int i = 0; i < 6; i++) dvv[i] = sdv[6 * L + i];

        float run = 1.f;
        #pragma unroll
        for (int i = 0; i < 6; i++) {
            float dist;
            if (i < 5)          dist = tb[i + 1] - tb[i];
            else if (L == 31)   dist = 1e10f;
            else                dist = t6 - tb[5];
            dist *= dnorm;
            alpha[i] = 1.f - __expf(-dvv[i] * dist);
            lex[i]   = run;                       // local exclusive product
            run *= (1.f - alpha[i] + 1e-10f);
        }
        // warp multiplicative exclusive scan of per-thread totals
        float inc = run;
        #pragma unroll
        for (int off = 1; off < 32; off <<= 1) {
            float n = __shfl_up_sync(0xffffffffu, inc, off);
            if (L >= off) inc *= n;
        }
        float wex = __shfl_up_sync(0xffffffffu, inc, 1);
        if (L == 0) wex = 1.f;

        #pragma unroll
        for (int i = 0; i < 6; i++) {
            const float T  = wex * lex[i];
            const float wt = alpha[i] * T;
            sw[6 * L + i] = wt;
            dep += wt * tb[i];
            op  += wt;
        }
    }
    __syncwarp();

    // ---- G: fused coalesced fp stores + rgb accumulation ----
    // element pairs e0 = 64*i + 2L (+1); channel c = (rho + slot)%3, rho = (2L)%3
    float A0 = 0.f, A1 = 0.f, A2 = 0.f;
    {
        const int rho = (2 * L) % 3;
        // rotated origin/direction: oR[q] = o[(rho+q)%3]
        const float oR0 = (rho == 0) ? ox : ((rho == 1) ? oy : oz);
        const float oR1 = (rho == 0) ? oy : ((rho == 1) ? oz : ox);
        const float oR2 = (rho == 0) ? oz : ((rho == 1) ? ox : oy);
        const float dR0 = (rho == 0) ? dx : ((rho == 1) ? dy : dz);
        const float dR1 = (rho == 0) ? dy : ((rho == 1) ? dz : dx);
        const float dR2 = (rho == 0) ? dz : ((rho == 1) ? dx : dy);
        float* fpb = out_fp + (size_t)ray * (NS * 3);

        #pragma unroll
        for (int i = 0; i < 9; i++) {
            const int e0  = 64 * i + 2 * L;
            const int s0  = e0 / 3;
            const int c0r = e0 - 3 * s0;
            const int s1  = s0 + (c0r == 2 ? 1 : 0);
            const float t0 = st[s0], t1 = st[s1];
            const float w0 = sw[s0], w1 = sw[s1];
            const int q0 = i % 3, q1 = (i + 1) % 3;   // compile-time slots
            const float o0 = (q0 == 0) ? oR0 : ((q0 == 1) ? oR1 : oR2);
            const float d0 = (q0 == 0) ? dR0 : ((q0 == 1) ? dR1 : dR2);
            const float o1 = (q1 == 0) ? oR0 : ((q1 == 1) ? oR1 : oR2);
            const float d1 = (q1 == 0) ? dR0 : ((q1 == 1) ? dR1 : dR2);
            *(float2*)(fpb + e0) = make_float2(o0 + d0 * t0, o1 + d1 * t1);
            const float g0 = w0 * cv[i].x;
            const float g1 = w1 * cv[i].y;
            if (q0 == 0) A0 += g0; else if (q0 == 1) A1 += g0; else A2 += g0;
            if (q1 == 0) A0 += g1; else if (q1 == 1) A1 += g1; else A2 += g1;
        }
    }

    // ---- H: final reductions (single warp, no shared) ----
    {
        const int i0 = (0 + L) % 3, i1 = (1 + L) % 3, i2 = (2 + L) % 3;
        float rC = (i0 == 0) ? A0 : ((i0 == 1) ? A1 : A2);
        float gC = (i1 == 0) ? A0 : ((i1 == 1) ? A1 : A2);
        float bC = (i2 == 0) ? A0 : ((i2 == 1) ? A1 : A2);
        #pragma unroll
        for (int off = 16; off; off >>= 1) {
            rC  += __shfl_xor_sync(0xffffffffu, rC,  off);
            gC  += __shfl_xor_sync(0xffffffffu, gC,  off);
            bC  += __shfl_xor_sync(0xffffffffu, bC,  off);
            dep += __shfl_xor_sync(0xffffffffu, dep, off);
            op  += __shfl_xor_sync(0xffffffffu, op,  off);
        }
        if (L == 0) {
            out_rgb[3 * ray + 0] = rC;
            out_rgb[3 * ray + 1] = gC;
            out_rgb[3 * ray + 2] = bC;
            out_depth[ray] = dep;
            out_op[ray]    = op;
        }
    }
}

extern "C" void kernel_launch(void* const* d_in, const int* in_sizes, int n_in,
                              void* d_out, int out_size)
{
    const float* ro     = (const float*)d_in[0];
    const float* rd     = (const float*)d_in[1];
    const float* cw     = (const float*)d_in[2];
    const float* ct     = (const float*)d_in[3];
    const float* u      = (const float*)d_in[4];
    const float* colors = (const float*)d_in[5];
    const float* dens   = (const float*)d_in[6];

    const int N = in_sizes[0] / 3;

    float* out       = (float*)d_out;
    float* out_rgb   = out;                 // [N,3]
    float* out_depth = out + (size_t)N * 3; // [N]
    float* out_op    = out_depth + N;       // [N]
    float* out_fp    = out_op + N;          // [N,NS,3]

    const int blocks = (N + RPB - 1) / RPB;
    gridnerf_kernel<<<blocks, 32 * RPB>>>(ro, rd, cw, ct, u, colors, dens,
                                          out_rgb, out_depth, out_op, out_fp, N);
}